// round 5
// baseline (speedup 1.0000x reference)
#include <cuda_runtime.h>
#include <cuda_bf16.h>
#include <stdint.h>

#define NUM_ROWS 16384
#define HDIM     2048
#define KSEL     4
#define NEXP     64
#define NTOT     (NUM_ROWS * KSEL)   /* 65536 expanded slots */
#define NCHUNK   512
#define CHUNK    (NTOT / NCHUNK)     /* 128 items per chunk */
#define NWARP    (CHUNK / 32)        /* 4 warps per chunk block */

/* output layout (floats) */
#define X_OFF   0
#define RI_OFF  ((size_t)NTOT * HDIM)                 /* 134217728 */
#define CNT_OFF (RI_OFF + NTOT)                        /* +65536 */
#define SC_OFF  (CNT_OFF + NEXP)                       /* +64 */

/* scratch (no cudaMalloc allowed) */
__device__ int g_chunkCounts[NCHUNK * NEXP];  /* K1: counts; K2: stable bases */
__device__ int g_rank[NTOT];                  /* intra-chunk stable rank      */

/* ---- K1: per-chunk histogram + intra-chunk stable rank ---- */
__global__ void __launch_bounds__(CHUNK) k_rank(const int* __restrict__ eidx) {
    __shared__ int shcnt[NWARP][NEXP];
    int t = threadIdx.x;
    int c = blockIdx.x;
    int w = t >> 5, lane = t & 31;

    for (int j = t; j < NWARP * NEXP; j += CHUNK)
        ((int*)shcnt)[j] = 0;
    __syncthreads();

    int i = c * CHUNK + t;
    int e = eidx[i];
    unsigned m = __match_any_sync(0xffffffffu, e);
    int rank = __popc(m & ((1u << lane) - 1));
    if (rank == 0) shcnt[w][e] = __popc(m);
    __syncthreads();

    int off = 0;
#pragma unroll
    for (int w2 = 0; w2 < NWARP; ++w2)
        if (w2 < w) off += shcnt[w2][e];
    g_rank[i] = off + rank;

    if (t < NEXP) {
        int s = 0;
#pragma unroll
        for (int w2 = 0; w2 < NWARP; ++w2) s += shcnt[w2][t];
        g_chunkCounts[c * NEXP + t] = s;
    }
}

/* ---- K2: parallel scan -> stable per-chunk/per-expert bases + counts ----
 * 1024 threads = 64 experts x 16 groups; each group owns 32 chunks.
 */
#define GRP 16
#define CPG (NCHUNK / GRP)   /* 32 chunks per group */
__global__ void __launch_bounds__(1024) k_scan(float* __restrict__ out) {
    __shared__ int tot[NEXP];
    __shared__ int offs[NEXP];
    int t = threadIdx.x;
    int e = t >> 4;           /* expert 0..63 */
    int g = t & (GRP - 1);    /* chunk-group 0..15 */

    int v[CPG];
    int partial = 0;
#pragma unroll
    for (int j = 0; j < CPG; ++j) {
        v[j] = g_chunkCounts[(g * CPG + j) * NEXP + e];
        partial += v[j];
    }

    /* inclusive scan of partials across the 16-lane segment */
    int inc = partial;
#pragma unroll
    for (int d = 1; d < GRP; d <<= 1) {
        int y = __shfl_up_sync(0xffffffffu, inc, d, GRP);
        if (g >= d) inc += y;
    }
    if (g == GRP - 1) tot[e] = inc;
    __syncthreads();

    if (t == 0) {
        int run = 0;
        for (int j = 0; j < NEXP; ++j) { offs[j] = run; run += tot[j]; }
    }
    __syncthreads();
    if (t < NEXP) out[CNT_OFF + t] = (float)tot[t];

    int run = offs[e] + (inc - partial);   /* exclusive base for this group */
#pragma unroll
    for (int j = 0; j < CPG; ++j) {
        g_chunkCounts[(g * CPG + j) * NEXP + e] = run;
        run += v[j];
    }
}

/* ---- K3: big gather copy + final dest resolve + small outputs ----
 * Loads of x are issued BEFORE the destination resolve (independent), and
 * all 4 float4 are held in registers to maximize per-thread MLP.
 */
__global__ void __launch_bounds__(128) k_copy(const float* __restrict__ x,
                                              const int* __restrict__ eidx,
                                              const float* __restrict__ scale,
                                              float* __restrict__ out) {
    int i = blockIdx.x;          /* expanded slot 0..NTOT-1 */
    int src = i >> 2;
    int t = threadIdx.x;

    const float4* __restrict__ s = (const float4*)(x + (size_t)src * HDIM);
    float4 v0 = s[t];
    float4 v1 = s[t + 128];
    float4 v2 = s[t + 256];
    float4 v3 = s[t + 384];

    int e = __ldg(eidx + i);
    int d = g_chunkCounts[(i >> 7) * NEXP + e] + g_rank[i];

    float4* __restrict__ o = (float4*)(out + X_OFF + (size_t)d * HDIM);
    o[t]       = v0;
    o[t + 128] = v1;
    o[t + 256] = v2;
    o[t + 384] = v3;

    if (t == 0) {
        out[RI_OFF + i] = (float)d;
        out[SC_OFF + d] = scale[src];
    }
}

extern "C" void kernel_launch(void* const* d_in, const int* in_sizes, int n_in,
                              void* d_out, int out_size) {
    const float* x     = (const float*)d_in[0];
    const int*   eidx  = (const int*)d_in[1];
    const float* scale = (const float*)d_in[2];
    float* out = (float*)d_out;

    k_rank<<<NCHUNK, CHUNK>>>(eidx);
    k_scan<<<1, 1024>>>(out);
    k_copy<<<NTOT, 128>>>(x, eidx, scale, out);
}